// round 6
// baseline (speedup 1.0000x reference)
#include <cuda_runtime.h>
#include <cstdint>
#include <cstddef>

// Scatter-mean message passing via single-pass padded-CSR build + per-node gather-reduce.
//   out[t] = mean over edges e with tgt[e]==t of x[src[e]]
// x: [N, 64] f32, edge_idx: [2, E] i32 (row 0 = src, row 1 = tgt)

#define F 64
#define MAX_N (1 << 17)      // >= 100000
#define SLOTS 64             // padded CSR row capacity (Poisson(16): P(deg>64) ~ 1e-20)
#define MAX_OVER 8192        // overflow spill capacity (correctness fallback)

typedef unsigned long long ull;

__device__ int g_cnt[MAX_N];                     // per-node edge count (true degree)
__device__ int g_sorted[(size_t)MAX_N * SLOTS];  // per-node src BYTE OFFSETS (src*256)
__device__ int g_over_src[MAX_OVER];             // overflow: src byte offsets
__device__ int g_over_tgt[MAX_OVER];
__device__ int g_over_cnt[1];

__device__ __forceinline__ void spill_edge(int soff, int d) {
    int op = atomicAdd(&g_over_cnt[0], 1);
    if (op < MAX_OVER) { g_over_src[op] = soff; g_over_tgt[op] = d; }
}

// Single build pass: 4 edges per thread via int4; 4 atomics issued before the
// 4 dependent scattered stores (atomic latency overlapped).
__global__ void fill_kernel(const int4* __restrict__ src4,
                            const int4* __restrict__ tgt4, int E4,
                            const int* __restrict__ src,
                            const int* __restrict__ tgt, int E) {
    int t = blockIdx.x * blockDim.x + threadIdx.x;
    if (t < E4) {
        int4 s = __ldg(&src4[t]);
        int4 d = __ldg(&tgt4[t]);
        int p0 = atomicAdd(&g_cnt[d.x], 1);
        int p1 = atomicAdd(&g_cnt[d.y], 1);
        int p2 = atomicAdd(&g_cnt[d.z], 1);
        int p3 = atomicAdd(&g_cnt[d.w], 1);
        if (p0 < SLOTS) g_sorted[(size_t)d.x * SLOTS + p0] = s.x << 8; else spill_edge(s.x << 8, d.x);
        if (p1 < SLOTS) g_sorted[(size_t)d.y * SLOTS + p1] = s.y << 8; else spill_edge(s.y << 8, d.y);
        if (p2 < SLOTS) g_sorted[(size_t)d.z * SLOTS + p2] = s.z << 8; else spill_edge(s.z << 8, d.z);
        if (p3 < SLOTS) g_sorted[(size_t)d.w * SLOTS + p3] = s.w << 8; else spill_edge(s.w << 8, d.w);
    }
    if (t == 0) {
        for (int e = E4 * 4; e < E; e++) {
            int d = tgt[e];
            int pos = atomicAdd(&g_cnt[d], 1);
            if (pos < SLOTS) g_sorted[(size_t)d * SLOTS + pos] = src[e] << 8;
            else spill_edge(src[e] << 8, d);
        }
    }
}

__device__ __forceinline__ ull f2add(ull a, ull b) {
    ull r;
    asm("add.rn.f32x2 %0, %1, %2;" : "=l"(r) : "l"(a), "l"(b));
    return r;
}
__device__ __forceinline__ ull f2mul(ull a, ull b) {
    ull r;
    asm("mul.rn.f32x2 %0, %1, %2;" : "=l"(r) : "l"(a), "l"(b));
    return r;
}

// One warp per node. Lane owns 8B (float2) of the 256B row.
// Per 16-edge chunk: 4 independent int4 idx loads up front (rows always have
// 64 valid slots, so no bounds check on idx loads), then 16 gathers issued
// together (predicated zero-fill past the degree) into 4 accumulators.
// Warp critical path ~= one idx latency + one gather latency per chunk.
__global__ void __launch_bounds__(256)
aggregate_kernel(const char* __restrict__ xbase,
                 float2* __restrict__ out2, int N) {
    int n = (blockIdx.x * blockDim.x + threadIdx.x) >> 5;
    int lane = threadIdx.x & 31;
    if (n >= N) return;

    int count = g_cnt[n];
    int m = count < SLOTS ? count : SLOTS;
    const int4* row4 = (const int4*)&g_sorted[(size_t)n * SLOTS];
    const char* xlane = xbase + (lane << 3);

    ull acc0 = 0, acc1 = 0, acc2 = 0, acc3 = 0;

    for (int base = 0; base < m; base += 16) {
        int rem = m - base;                     // > 0
        int b4 = base >> 2;
        // All 4 idx loads issue immediately (in-bounds by construction).
        int4 q0 = __ldg(&row4[b4 + 0]);
        int4 q1 = __ldg(&row4[b4 + 1]);
        int4 q2 = __ldg(&row4[b4 + 2]);
        int4 q3 = __ldg(&row4[b4 + 3]);

        int idx[16] = {q0.x, q0.y, q0.z, q0.w,  q1.x, q1.y, q1.z, q1.w,
                       q2.x, q2.y, q2.z, q2.w,  q3.x, q3.y, q3.z, q3.w};

        ull v[16];
        #pragma unroll
        for (int j = 0; j < 16; j++) {
            v[j] = 0;
            if (j < rem)
                v[j] = __ldg((const ull*)(xlane + (size_t)(unsigned)idx[j]));
        }
        #pragma unroll
        for (int j = 0; j < 16; j += 4) {
            acc0 = f2add(acc0, v[j + 0]);
            acc1 = f2add(acc1, v[j + 1]);
            acc2 = f2add(acc2, v[j + 2]);
            acc3 = f2add(acc3, v[j + 3]);
        }
    }

    // Overflow fallback (cold: only if some node's degree exceeded SLOTS).
    if (count > SLOTS) {
        int oc = g_over_cnt[0];
        for (int i = 0; i < oc; i++) {
            if (g_over_tgt[i] == n) {
                int s = g_over_src[i];
                acc0 = f2add(acc0, __ldg((const ull*)(xlane + (size_t)(unsigned)s)));
            }
        }
    }

    acc0 = f2add(f2add(acc0, acc1), f2add(acc2, acc3));

    float inv = count > 0 ? 1.0f / (float)count : 0.0f;
    ull inv2;
    asm("mov.b64 %0, {%1, %1};" : "=l"(inv2) : "f"(inv));
    ull o = f2mul(acc0, inv2);

    unsigned int lo, hi;
    asm("mov.b64 {%0, %1}, %2;" : "=r"(lo), "=r"(hi) : "l"(o));
    float2 ov;
    ov.x = __uint_as_float(lo);
    ov.y = __uint_as_float(hi);
    out2[(size_t)n * 32 + lane] = ov;
}

extern "C" void kernel_launch(void* const* d_in, const int* in_sizes, int n_in,
                              void* d_out, int out_size) {
    const float* x = (const float*)d_in[0];
    const int* edge_idx = (const int*)d_in[1];

    int E = in_sizes[1] / 2;
    int N = out_size / F;

    const int* src = edge_idx;       // row 0
    const int* tgt = edge_idx + E;   // row 1

    // Zero scratch counters via memset nodes.
    void* cnt_ptr = nullptr;
    void* over_ptr = nullptr;
    cudaGetSymbolAddress(&cnt_ptr, g_cnt);
    cudaGetSymbolAddress(&over_ptr, g_over_cnt);
    cudaMemsetAsync(cnt_ptr, 0, (size_t)N * sizeof(int));
    cudaMemsetAsync(over_ptr, 0, sizeof(int));

    const int T = 256;

    int E4 = E / 4;
    int fill_blocks = (E4 + T - 1) / T;
    if (fill_blocks < 1) fill_blocks = 1;
    fill_kernel<<<fill_blocks, T>>>((const int4*)src, (const int4*)tgt, E4,
                                    src, tgt, E);

    long long total = (long long)N * 32;
    aggregate_kernel<<<(int)((total + T - 1) / T), T>>>(
        (const char*)x, (float2*)d_out, N);
}

// round 7
// speedup vs baseline: 1.1182x; 1.1182x over previous
#include <cuda_runtime.h>
#include <cstdint>
#include <cstddef>

// Scatter-mean message passing via single-pass padded-CSR build + per-node gather-reduce.
//   out[t] = mean over edges e with tgt[e]==t of x[src[e]]
// x: [N, 64] f32, edge_idx: [2, E] i32 (row 0 = src, row 1 = tgt)

#define F 64
#define MAX_N (1 << 17)      // >= 100000
#define SLOTS 64             // padded CSR row capacity (Poisson(16): P(deg>64) ~ 1e-20)
#define MAX_OVER 8192        // overflow spill capacity (correctness fallback)

typedef unsigned long long ull;

__device__ int g_cnt[MAX_N];                     // per-node edge count (true degree)
__device__ int g_sorted[(size_t)MAX_N * SLOTS];  // per-node src BYTE OFFSETS (src*256)
__device__ int g_over_src[MAX_OVER];             // overflow: src byte offsets
__device__ int g_over_tgt[MAX_OVER];
__device__ int g_over_cnt[1];

__device__ __forceinline__ void spill_edge(int soff, int d) {
    int op = atomicAdd(&g_over_cnt[0], 1);
    if (op < MAX_OVER) { g_over_src[op] = soff; g_over_tgt[op] = d; }
}

// Single build pass: 4 edges per thread via int4; 4 atomics issued before the
// 4 dependent scattered stores (atomic latency overlapped).
__global__ void fill_kernel(const int4* __restrict__ src4,
                            const int4* __restrict__ tgt4, int E4,
                            const int* __restrict__ src,
                            const int* __restrict__ tgt, int E) {
    int t = blockIdx.x * blockDim.x + threadIdx.x;
    if (t < E4) {
        int4 s = __ldg(&src4[t]);
        int4 d = __ldg(&tgt4[t]);
        int p0 = atomicAdd(&g_cnt[d.x], 1);
        int p1 = atomicAdd(&g_cnt[d.y], 1);
        int p2 = atomicAdd(&g_cnt[d.z], 1);
        int p3 = atomicAdd(&g_cnt[d.w], 1);
        if (p0 < SLOTS) g_sorted[(size_t)d.x * SLOTS + p0] = s.x << 8; else spill_edge(s.x << 8, d.x);
        if (p1 < SLOTS) g_sorted[(size_t)d.y * SLOTS + p1] = s.y << 8; else spill_edge(s.y << 8, d.y);
        if (p2 < SLOTS) g_sorted[(size_t)d.z * SLOTS + p2] = s.z << 8; else spill_edge(s.z << 8, d.z);
        if (p3 < SLOTS) g_sorted[(size_t)d.w * SLOTS + p3] = s.w << 8; else spill_edge(s.w << 8, d.w);
    }
    if (t == 0) {
        for (int e = E4 * 4; e < E; e++) {
            int d = tgt[e];
            int pos = atomicAdd(&g_cnt[d], 1);
            if (pos < SLOTS) g_sorted[(size_t)d * SLOTS + pos] = src[e] << 8;
            else spill_edge(src[e] << 8, d);
        }
    }
}

__device__ __forceinline__ ull f2add(ull a, ull b) {
    ull r;
    asm("add.rn.f32x2 %0, %1, %2;" : "=l"(r) : "l"(a), "l"(b));
    return r;
}
__device__ __forceinline__ ull f2mul(ull a, ull b) {
    ull r;
    asm("mul.rn.f32x2 %0, %1, %2;" : "=l"(r) : "l"(a), "l"(b));
    return r;
}

// One warp per node. Lane owns 8B (float2) of the 256B row.
// 4-deep unroll with SCALAR index loads: 4 independent idx->gather chains per
// iteration, schedulable/pipelinable by ptxas across iterations. Low regs,
// high occupancy (the R2 recipe, widened).
__global__ void __launch_bounds__(256)
aggregate_kernel(const char* __restrict__ xbase,
                 float2* __restrict__ out2, int N) {
    int n = (blockIdx.x * blockDim.x + threadIdx.x) >> 5;
    int lane = threadIdx.x & 31;
    if (n >= N) return;

    int count = g_cnt[n];
    int m = count < SLOTS ? count : SLOTS;
    const int* row = &g_sorted[(size_t)n * SLOTS];
    const char* xlane = xbase + (lane << 3);

    ull a0 = 0, a1 = 0, a2 = 0, a3 = 0;

    int k = 0;
    for (; k + 4 <= m; k += 4) {
        int s0 = __ldg(&row[k + 0]);
        int s1 = __ldg(&row[k + 1]);
        int s2 = __ldg(&row[k + 2]);
        int s3 = __ldg(&row[k + 3]);
        ull v0 = __ldg((const ull*)(xlane + (size_t)(unsigned)s0));
        ull v1 = __ldg((const ull*)(xlane + (size_t)(unsigned)s1));
        ull v2 = __ldg((const ull*)(xlane + (size_t)(unsigned)s2));
        ull v3 = __ldg((const ull*)(xlane + (size_t)(unsigned)s3));
        a0 = f2add(a0, v0);
        a1 = f2add(a1, v1);
        a2 = f2add(a2, v2);
        a3 = f2add(a3, v3);
    }
    for (; k < m; k++) {
        int s = __ldg(&row[k]);
        a0 = f2add(a0, __ldg((const ull*)(xlane + (size_t)(unsigned)s)));
    }

    // Overflow fallback (cold: only if some node's degree exceeded SLOTS).
    if (count > SLOTS) {
        int oc = g_over_cnt[0];
        for (int i = 0; i < oc; i++) {
            if (g_over_tgt[i] == n) {
                int s = g_over_src[i];
                a0 = f2add(a0, __ldg((const ull*)(xlane + (size_t)(unsigned)s)));
            }
        }
    }

    a0 = f2add(f2add(a0, a1), f2add(a2, a3));

    float inv = count > 0 ? 1.0f / (float)count : 0.0f;
    ull inv2;
    asm("mov.b64 %0, {%1, %1};" : "=l"(inv2) : "f"(inv));
    ull o = f2mul(a0, inv2);

    unsigned int lo, hi;
    asm("mov.b64 {%0, %1}, %2;" : "=r"(lo), "=r"(hi) : "l"(o));
    float2 ov;
    ov.x = __uint_as_float(lo);
    ov.y = __uint_as_float(hi);
    out2[(size_t)n * 32 + lane] = ov;
}

extern "C" void kernel_launch(void* const* d_in, const int* in_sizes, int n_in,
                              void* d_out, int out_size) {
    const float* x = (const float*)d_in[0];
    const int* edge_idx = (const int*)d_in[1];

    int E = in_sizes[1] / 2;
    int N = out_size / F;

    const int* src = edge_idx;       // row 0
    const int* tgt = edge_idx + E;   // row 1

    // Zero scratch counters via memset nodes.
    void* cnt_ptr = nullptr;
    void* over_ptr = nullptr;
    cudaGetSymbolAddress(&cnt_ptr, g_cnt);
    cudaGetSymbolAddress(&over_ptr, g_over_cnt);
    cudaMemsetAsync(cnt_ptr, 0, (size_t)N * sizeof(int));
    cudaMemsetAsync(over_ptr, 0, sizeof(int));

    const int T = 256;

    int E4 = E / 4;
    int fill_blocks = (E4 + T - 1) / T;
    if (fill_blocks < 1) fill_blocks = 1;
    fill_kernel<<<fill_blocks, T>>>((const int4*)src, (const int4*)tgt, E4,
                                    src, tgt, E);

    long long total = (long long)N * 32;
    aggregate_kernel<<<(int)((total + T - 1) / T), T>>>(
        (const char*)x, (float2*)d_out, N);
}

// round 8
// speedup vs baseline: 1.2397x; 1.1086x over previous
#include <cuda_runtime.h>
#include <cstdint>
#include <cstddef>

// Scatter-mean message passing via single-pass padded-CSR build + per-node gather-reduce.
//   out[t] = mean over edges e with tgt[e]==t of x[src[e]]
// x: [N, 64] f32, edge_idx: [2, E] i32 (row 0 = src, row 1 = tgt)

#define F 64
#define MAX_N (1 << 17)      // >= 100000
#define SLOTS 32             // padded CSR row capacity = 128B = one L2 line
#define MAX_OVER 16384       // overflow spill capacity (correctness fallback)

typedef unsigned long long ull;

__device__ int g_cnt[MAX_N];                     // per-node edge count (true degree)
__device__ int g_sorted[(size_t)MAX_N * SLOTS];  // per-node src BYTE OFFSETS (src*256)
__device__ int g_over_src[MAX_OVER];             // overflow: src byte offsets
__device__ int g_over_tgt[MAX_OVER];
__device__ int g_over_cnt[1];

__device__ __forceinline__ void spill_edge(int soff, int d) {
    int op = atomicAdd(&g_over_cnt[0], 1);
    if (op < MAX_OVER) { g_over_src[op] = soff; g_over_tgt[op] = d; }
}

// Single build pass: 4 edges per thread via int4; 4 atomics issued before the
// 4 dependent scattered stores (atomic latency overlapped).
__global__ void fill_kernel(const int4* __restrict__ src4,
                            const int4* __restrict__ tgt4, int E4,
                            const int* __restrict__ src,
                            const int* __restrict__ tgt, int E) {
    int t = blockIdx.x * blockDim.x + threadIdx.x;
    if (t < E4) {
        int4 s = __ldg(&src4[t]);
        int4 d = __ldg(&tgt4[t]);
        int p0 = atomicAdd(&g_cnt[d.x], 1);
        int p1 = atomicAdd(&g_cnt[d.y], 1);
        int p2 = atomicAdd(&g_cnt[d.z], 1);
        int p3 = atomicAdd(&g_cnt[d.w], 1);
        if (p0 < SLOTS) g_sorted[(size_t)d.x * SLOTS + p0] = s.x << 8; else spill_edge(s.x << 8, d.x);
        if (p1 < SLOTS) g_sorted[(size_t)d.y * SLOTS + p1] = s.y << 8; else spill_edge(s.y << 8, d.y);
        if (p2 < SLOTS) g_sorted[(size_t)d.z * SLOTS + p2] = s.z << 8; else spill_edge(s.z << 8, d.z);
        if (p3 < SLOTS) g_sorted[(size_t)d.w * SLOTS + p3] = s.w << 8; else spill_edge(s.w << 8, d.w);
    }
    if (t == 0) {
        for (int e = E4 * 4; e < E; e++) {
            int d = tgt[e];
            int pos = atomicAdd(&g_cnt[d], 1);
            if (pos < SLOTS) g_sorted[(size_t)d * SLOTS + pos] = src[e] << 8;
            else spill_edge(src[e] << 8, d);
        }
    }
}

__device__ __forceinline__ ull f2add(ull a, ull b) {
    ull r;
    asm("add.rn.f32x2 %0, %1, %2;" : "=l"(r) : "l"(a), "l"(b));
    return r;
}
__device__ __forceinline__ ull f2mul(ull a, ull b) {
    ull r;
    asm("mul.rn.f32x2 %0, %1, %2;" : "=l"(r) : "l"(a), "l"(b));
    return r;
}

// One warp per node. Lane owns 8B (float2) of the 256B row.
// R2-recipe loop: unroll 2, scalar warp-uniform index loads, 2 accumulators.
// Minimal per-warp front-batched MLP at maximal occupancy — measured optimum
// against cross-CTA L1tex queue contention (R2/R5/R6/R7 ladder).
__global__ void __launch_bounds__(256)
aggregate_kernel(const char* __restrict__ xbase,
                 float2* __restrict__ out2, int N) {
    int n = (blockIdx.x * blockDim.x + threadIdx.x) >> 5;
    int lane = threadIdx.x & 31;
    if (n >= N) return;

    int count = g_cnt[n];
    int m = count < SLOTS ? count : SLOTS;
    const int* row = &g_sorted[(size_t)n * SLOTS];
    const char* xlane = xbase + (lane << 3);

    ull a0 = 0, a1 = 0;

    int k = 0;
    for (; k + 2 <= m; k += 2) {
        int s0 = __ldg(&row[k + 0]);
        int s1 = __ldg(&row[k + 1]);
        ull v0 = __ldg((const ull*)(xlane + (size_t)(unsigned)s0));
        ull v1 = __ldg((const ull*)(xlane + (size_t)(unsigned)s1));
        a0 = f2add(a0, v0);
        a1 = f2add(a1, v1);
    }
    if (k < m) {
        int s = __ldg(&row[k]);
        a0 = f2add(a0, __ldg((const ull*)(xlane + (size_t)(unsigned)s)));
    }

    // Overflow fallback (cold: only if some node's degree exceeded SLOTS).
    if (count > SLOTS) {
        int oc = g_over_cnt[0];
        for (int i = 0; i < oc; i++) {
            if (g_over_tgt[i] == n) {
                int s = g_over_src[i];
                a0 = f2add(a0, __ldg((const ull*)(xlane + (size_t)(unsigned)s)));
            }
        }
    }

    a0 = f2add(a0, a1);

    float inv = count > 0 ? 1.0f / (float)count : 0.0f;
    ull inv2;
    asm("mov.b64 %0, {%1, %1};" : "=l"(inv2) : "f"(inv));
    ull o = f2mul(a0, inv2);

    unsigned int lo, hi;
    asm("mov.b64 {%0, %1}, %2;" : "=r"(lo), "=r"(hi) : "l"(o));
    float2 ov;
    ov.x = __uint_as_float(lo);
    ov.y = __uint_as_float(hi);
    out2[(size_t)n * 32 + lane] = ov;
}

extern "C" void kernel_launch(void* const* d_in, const int* in_sizes, int n_in,
                              void* d_out, int out_size) {
    const float* x = (const float*)d_in[0];
    const int* edge_idx = (const int*)d_in[1];

    int E = in_sizes[1] / 2;
    int N = out_size / F;

    const int* src = edge_idx;       // row 0
    const int* tgt = edge_idx + E;   // row 1

    // Zero scratch counters via memset nodes.
    void* cnt_ptr = nullptr;
    void* over_ptr = nullptr;
    cudaGetSymbolAddress(&cnt_ptr, g_cnt);
    cudaGetSymbolAddress(&over_ptr, g_over_cnt);
    cudaMemsetAsync(cnt_ptr, 0, (size_t)N * sizeof(int));
    cudaMemsetAsync(over_ptr, 0, sizeof(int));

    const int T = 256;

    int E4 = E / 4;
    int fill_blocks = (E4 + T - 1) / T;
    if (fill_blocks < 1) fill_blocks = 1;
    fill_kernel<<<fill_blocks, T>>>((const int4*)src, (const int4*)tgt, E4,
                                    src, tgt, E);

    long long total = (long long)N * 32;
    aggregate_kernel<<<(int)((total + T - 1) / T), T>>>(
        (const char*)x, (float2*)d_out, N);
}